// round 11
// baseline (speedup 1.0000x reference)
#include <cuda_runtime.h>
#include <cuda_bf16.h>
#include <cstdint>

#define NN 50000
#define EE 400000
#define TT 4
#define DIN 64
#define DD 128
#define BG 64
#define NSTEPS 8
#define RTILES ((NN + 127) / 128)   // 391
#define NT (NN * TT)                // 200000 buckets (dst*4 + etype)
#define NBS ((NT + 1023) / 1024)    // 196 scan blocks
#define PLANE ((size_t)(NN + 128) * DD)   // padded s-plane stride

// ---------------- device scratch ----------------
__device__ float g_h1[NN * DD];                 // residual (fp32)
__device__ float g_hf[NN * DD];                 // current h (fp32, for gather)
__device__ float g_rs[NN * DD];
__device__ float g_zs[NN * DD];
__device__ float g_in[NN * DD];
__device__ float g_hn[NN * DD];
__device__ float g_feats[BG * DD];
// split-state buffers (padded for OOB tile loads)
__device__ __nv_bfloat16 g_hh[(NN + 128) * DD];
__device__ __nv_bfloat16 g_hl[(NN + 128) * DD];
__device__ __nv_bfloat16 g_ah[(NN + 128) * DD];
__device__ __nv_bfloat16 g_al[(NN + 128) * DD];
// s planes: [t][d][128] bf16 hi/lo
__device__ __nv_bfloat16 g_sh[4 * ((NN + 128) * DD)];
__device__ __nv_bfloat16 g_sl[4 * ((NN + 128) * DD)];
// CSR by (dst,etype)
__device__ int g_cnt [NT];
__device__ int g_scan[NT];
__device__ int g_part [256];
__device__ int g_part2[256];
__device__ int g_eoff[EE];
__device__ int g_gsrc[EE];               // payload: src*128
// prepped bf16 hi/lo weights, B layout [col][k]
__device__ __nv_bfloat16 g_Wt_hi [TT * DD * DD];
__device__ __nv_bfloat16 g_Wt_lo [TT * DD * DD];
__device__ __nv_bfloat16 g_Bih_hi[3 * DD * DD];
__device__ __nv_bfloat16 g_Bih_lo[3 * DD * DD];
__device__ __nv_bfloat16 g_Bhh_hi[3 * DD * DD];
__device__ __nv_bfloat16 g_Bhh_lo[3 * DD * DD];

// ---------------- helpers ----------------
__device__ __forceinline__ uint32_t smem_u32(const void* p) {
    return (uint32_t)__cvta_generic_to_shared(p);
}
__device__ __forceinline__ void ldsm_x4(uint32_t* r, uint32_t addr) {
    asm volatile("ldmatrix.sync.aligned.m8n8.x4.shared.b16 {%0,%1,%2,%3}, [%4];"
                 : "=r"(r[0]), "=r"(r[1]), "=r"(r[2]), "=r"(r[3]) : "r"(addr));
}
__device__ __forceinline__ void mma16816(float* d, const uint32_t* a, const uint32_t* b) {
    asm volatile(
        "mma.sync.aligned.m16n8k16.row.col.f32.bf16.bf16.f32 "
        "{%0,%1,%2,%3}, {%4,%5,%6,%7}, {%8,%9}, {%0,%1,%2,%3};"
        : "+f"(d[0]), "+f"(d[1]), "+f"(d[2]), "+f"(d[3])
        : "r"(a[0]), "r"(a[1]), "r"(a[2]), "r"(a[3]), "r"(b[0]), "r"(b[1]));
}
__device__ __forceinline__ void cp16(uint32_t dst, const void* src) {
    asm volatile("cp.async.cg.shared.global [%0], [%1], 16;" :: "r"(dst), "l"(src));
}
#define CP_COMMIT() asm volatile("cp.async.commit_group;" ::: "memory")
#define CP_WAIT(n)  asm volatile("cp.async.wait_group %0;" :: "n"(n) : "memory")

#define TROW 136
#define RB   (TROW * 2)            // 272
#define AT128 (128 * RB)           // 34816
#define SM6   (6 * AT128)          // 208896

__device__ __forceinline__ void split2(float v, __nv_bfloat16& h, __nv_bfloat16& l) {
    h = __float2bfloat16(v);
    l = __float2bfloat16(v - __bfloat162float(h));
}

// async copy of a 128x128 bf16 tile-pair (hi + lo), row-major [128][128] source
__device__ __forceinline__ void tile_async(char* bh, char* bl,
        const __nv_bfloat16* __restrict__ Bh, const __nv_bfloat16* __restrict__ Bl, int tid) {
    uint32_t uh = smem_u32(bh), ul = smem_u32(bl);
#pragma unroll
    for (int i = 0; i < 8; i++) {
        int f = tid + 256 * i;
        int r = f >> 4, c8 = (f & 15) * 8;
        uint32_t off = r * RB + c8 * 2;
        cp16(uh + off, Bh + (size_t)r * DD + c8);
        cp16(ul + off, Bl + (size_t)r * DD + c8);
    }
}

// 3-term split K=128 accumulate into acc[2][8][4] (proven round-4 inner loop)
__device__ __forceinline__ void mma_accum_3term(float acc[2][8][4],
        uint32_t uAH, uint32_t uAL, uint32_t uBH, uint32_t uBL,
        uint32_t aoff, uint32_t boff) {
#pragma unroll
    for (int t = 0; t < 3; t++) {
        uint32_t ua = (t < 2) ? uAH : uAL;
        uint32_t ub = (t == 1) ? uBL : uBH;
#pragma unroll
        for (int k = 0; k < 8; k++) {
            uint32_t kb = k * 32;
            uint32_t afr[2][4], bfr[4][4];
            ldsm_x4(afr[0], ua + aoff + kb);
            ldsm_x4(afr[1], ua + aoff + kb + 16 * RB);
#pragma unroll
            for (int ni = 0; ni < 4; ni++)
                ldsm_x4(bfr[ni], ub + boff + kb + ni * 16 * RB);
#pragma unroll
            for (int mi = 0; mi < 2; mi++)
#pragma unroll
                for (int ni = 0; ni < 4; ni++) {
                    mma16816(acc[mi][ni * 2 + 0], afr[mi], &bfr[ni][0]);
                    mma16816(acc[mi][ni * 2 + 1], afr[mi], &bfr[ni][2]);
                }
        }
    }
}
__device__ __forceinline__ void zero_acc(float acc[2][8][4]) {
#pragma unroll
    for (int mi = 0; mi < 2; mi++)
#pragma unroll
        for (int n8 = 0; n8 < 8; n8++)
#pragma unroll
            for (int j = 0; j < 4; j++) acc[mi][n8][j] = 0.f;
}

// ---------------- fused prologue prep (launch 0) ----------------
__global__ void fused_prep(const float* __restrict__ features,
                           const float* __restrict__ Wmsg,
                           const float* __restrict__ wih,
                           const float* __restrict__ whh) {
    int idx = blockIdx.x * blockDim.x + threadIdx.x;
    if (idx < TT * DD * DD) {
        int t = idx >> 14, rem = idx & 16383, e = rem >> 7, d = rem & 127;
        float w = Wmsg[t * 16384 + d * 128 + e];
        __nv_bfloat16 hi, lo;
        split2(w, hi, lo);
        g_Wt_hi[idx] = hi; g_Wt_lo[idx] = lo;
    }
    if (idx < 3 * DD * DD) {
        int c = idx >> 7, k = idx & 127;
        __nv_bfloat16 hi, lo;
        split2(wih[k * 384 + c], hi, lo);
        g_Bih_hi[idx] = hi; g_Bih_lo[idx] = lo;
        split2(whh[k * 384 + c], hi, lo);
        g_Bhh_hi[idx] = hi; g_Bhh_lo[idx] = lo;
    }
    if (idx < NT) g_cnt[idx] = 0;
    if (idx < NN * DD) {
        int n = idx >> 7, j = idx & 127;
        float v = (j < DIN) ? features[n * DIN + j] : 0.f;
        g_h1[idx] = v;
        g_hf[idx] = v;
        __nv_bfloat16 hi, lo;
        split2(v, hi, lo);
        g_hh[idx] = hi; g_hl[idx] = lo;
    }
}

// ---------------- CSR build ----------------
__global__ void count_kernel(const int* __restrict__ dst, const int* __restrict__ et) {
    int e = blockIdx.x * blockDim.x + threadIdx.x;
    if (e >= EE) return;
    g_eoff[e] = atomicAdd(&g_cnt[dst[e] * 4 + et[e]], 1);
}
__global__ void scan_a_kernel() {
    __shared__ int s[1024];
    int b = blockIdx.x, t = threadIdx.x;
    int n = b * 1024 + t;
    int v = (n < NT) ? g_cnt[n] : 0;
    s[t] = v;
    __syncthreads();
    for (int d = 1; d < 1024; d <<= 1) {
        int x = (t >= d) ? s[t - d] : 0;
        __syncthreads();
        s[t] += x;
        __syncthreads();
    }
    if (n < NT) g_scan[n] = s[t] - v;
    if (t == 1023) g_part[b] = s[1023];
}
__global__ void scan_b_kernel() {
    __shared__ int s[256];
    int t = threadIdx.x;
    int v = (t < NBS) ? g_part[t] : 0;
    s[t] = v;
    __syncthreads();
    for (int d = 1; d < 256; d <<= 1) {
        int x = (t >= d) ? s[t - d] : 0;
        __syncthreads();
        s[t] += x;
        __syncthreads();
    }
    g_part2[t] = s[t] - v;
}
__global__ void fill_kernel(const int* __restrict__ src, const int* __restrict__ dst,
                            const int* __restrict__ et) {
    int e = blockIdx.x * blockDim.x + threadIdx.x;
    if (e >= EE) return;
    int b = dst[e] * 4 + et[e];
    int pos = g_scan[b] + g_part2[b >> 10] + g_eoff[e];
    g_gsrc[pos] = src[e] * DD;
}

// ---------------- gather_s: s_t[d] = sum h[src] over bucket ------------
__global__ __launch_bounds__(256) void gather_s() {
    int b = blockIdx.x * 8 + (threadIdx.x >> 5);
    if (b >= NT) return;
    int lane = threadIdx.x & 31;
    int lo = g_scan[b] + g_part2[b >> 10];
    int hi = (b == NT - 1) ? EE : (g_scan[b + 1] + g_part2[(b + 1) >> 10]);
    float4 a0 = make_float4(0.f, 0.f, 0.f, 0.f);
    float4 a1 = make_float4(0.f, 0.f, 0.f, 0.f);
    int i = lo;
    for (; i + 1 < hi; i += 2) {
        int s0 = g_gsrc[i], s1 = g_gsrc[i + 1];
        float4 v0 = *(const float4*)&g_hf[s0 + lane * 4];
        float4 v1 = *(const float4*)&g_hf[s1 + lane * 4];
        a0.x += v0.x; a0.y += v0.y; a0.z += v0.z; a0.w += v0.w;
        a1.x += v1.x; a1.y += v1.y; a1.z += v1.z; a1.w += v1.w;
    }
    if (i < hi) {
        int s0 = g_gsrc[i];
        float4 v0 = *(const float4*)&g_hf[s0 + lane * 4];
        a0.x += v0.x; a0.y += v0.y; a0.z += v0.z; a0.w += v0.w;
    }
    a0.x += a1.x; a0.y += a1.y; a0.z += a1.z; a0.w += a1.w;

    __nv_bfloat16 h0, l0, h1c, l1c, h2, l2, h3, l3;
    split2(a0.x, h0, l0); split2(a0.y, h1c, l1c);
    split2(a0.z, h2, l2); split2(a0.w, h3, l3);
    __nv_bfloat162 hp0 = {h0, h1c}, hp1 = {h2, h3};
    __nv_bfloat162 lp0 = {l0, l1c}, lp1 = {l2, l3};
    int d = b >> 2, t = b & 3;
    size_t o = (size_t)t * PLANE + (size_t)d * DD + lane * 4;
    *(uint2*)(g_sh + o) = make_uint2(*(uint32_t*)&hp0, *(uint32_t*)&hp1);
    *(uint2*)(g_sl + o) = make_uint2(*(uint32_t*)&lp0, *(uint32_t*)&lp1);
}

// ---------------- msg GEMM: a = sum_t s_t @ W_t^T + cnt_t * b_t --------
__global__ __launch_bounds__(256, 1) void msg_kernel(const float* __restrict__ bmsg) {
    extern __shared__ char smem[];
    char* sA[2][2] = {{smem, smem + AT128}, {smem + 2 * AT128, smem + 3 * AT128}};
    char* sBH = smem + 4 * AT128;
    char* sBL = smem + 5 * AT128;
    const int tid = threadIdx.x, wid = tid >> 5, lane = tid & 31;
    const int wm = wid & 3, wn = wid >> 2;
    const int row0 = blockIdx.x * 128;

    // prologue: A(0) then B(0)
    tile_async(sA[0][0], sA[0][1], g_sh + (size_t)row0 * DD, g_sl + (size_t)row0 * DD, tid);
    CP_COMMIT();
    tile_async(sBH, sBL, g_Wt_hi, g_Wt_lo, tid);
    CP_COMMIT();

    const uint32_t aoff = (uint32_t)((wm * 32 + (lane & 15)) * RB + (lane >> 4) * 16);
    const uint32_t boff = (uint32_t)((wn * 64 + ((lane >> 4) & 1) * 8 + (lane & 7)) * RB
                                     + ((lane >> 3) & 1) * 16);
    const uint32_t uA[2][2] = {{smem_u32(sA[0][0]), smem_u32(sA[0][1])},
                               {smem_u32(sA[1][0]), smem_u32(sA[1][1])}};
    const uint32_t uBH = smem_u32(sBH), uBL = smem_u32(sBL);

    float acc[2][8][4];
    zero_acc(acc);

    int buf = 0;
#pragma unroll 1
    for (int t = 0; t < 4; t++) {
        if (t < 3) {
            // prefetch A(t+1) while waiting for A(t)+B(t)
            tile_async(sA[buf ^ 1][0], sA[buf ^ 1][1],
                       g_sh + (size_t)(t + 1) * PLANE + (size_t)row0 * DD,
                       g_sl + (size_t)(t + 1) * PLANE + (size_t)row0 * DD, tid);
            CP_COMMIT();
            CP_WAIT(1);
        } else {
            CP_WAIT(0);
        }
        __syncthreads();
        mma_accum_3term(acc, uA[buf][0], uA[buf][1], uBH, uBL, aoff, boff);
        __syncthreads();
        if (t < 3) {
            tile_async(sBH, sBL, g_Wt_hi + (t + 1) * 16384, g_Wt_lo + (t + 1) * 16384, tid);
            CP_COMMIT();
        }
        buf ^= 1;
    }

    // epilogue: a = acc + sum_t cnt_t * b_t ; write split bf16
#pragma unroll
    for (int mi = 0; mi < 2; mi++) {
        int r0 = row0 + wm * 32 + mi * 16 + (lane >> 2);
        float cA[4] = {0.f, 0.f, 0.f, 0.f}, cB[4] = {0.f, 0.f, 0.f, 0.f};
        if (r0 < NN) {
            int4 c = *(const int4*)&g_cnt[r0 * 4];
            cA[0] = (float)c.x; cA[1] = (float)c.y; cA[2] = (float)c.z; cA[3] = (float)c.w;
        }
        if (r0 + 8 < NN) {
            int4 c = *(const int4*)&g_cnt[(r0 + 8) * 4];
            cB[0] = (float)c.x; cB[1] = (float)c.y; cB[2] = (float)c.z; cB[3] = (float)c.w;
        }
#pragma unroll
        for (int n8 = 0; n8 < 8; n8++) {
            int col = wn * 64 + n8 * 8 + (lane & 3) * 2;
            float k0a = 0.f, k1a = 0.f, k0b = 0.f, k1b = 0.f;
#pragma unroll
            for (int t = 0; t < 4; t++) {
                float b0 = __ldg(&bmsg[t * 128 + col]), b1 = __ldg(&bmsg[t * 128 + col + 1]);
                k0a += cA[t] * b0; k1a += cA[t] * b1;
                k0b += cB[t] * b0; k1b += cB[t] * b1;
            }
            if (r0 < NN) {
                float v0 = acc[mi][n8][0] + k0a, v1 = acc[mi][n8][1] + k1a;
                __nv_bfloat16 h0, l0, h1, l1;
                split2(v0, h0, l0); split2(v1, h1, l1);
                __nv_bfloat162 hp = {h0, h1}, lp = {l0, l1};
                size_t o = (size_t)r0 * DD + col;
                *(uint32_t*)(g_ah + o) = *(uint32_t*)&hp;
                *(uint32_t*)(g_al + o) = *(uint32_t*)&lp;
            }
            if (r0 + 8 < NN) {
                float v0 = acc[mi][n8][2] + k0b, v1 = acc[mi][n8][3] + k1b;
                __nv_bfloat16 h0, l0, h1, l1;
                split2(v0, h0, l0); split2(v1, h1, l1);
                __nv_bfloat162 hp = {h0, h1}, lp = {l0, l1};
                size_t o = (size_t)(r0 + 8) * DD + col;
                *(uint32_t*)(g_ah + o) = *(uint32_t*)&hp;
                *(uint32_t*)(g_al + o) = *(uint32_t*)&lp;
            }
        }
    }
}

// ---------------- gates: grid (391, 4), async fills (round-10) ----------
// y=0: rs = a@ih_r + h@hh_r ; y=1: zs ; y=2: in = a@ih_n ; y=3: hn = h@hh_n
__global__ __launch_bounds__(256, 1) void gates_tc() {
    extern __shared__ char smem[];
    char* sAaH = smem;
    char* sAaL = smem + AT128;
    char* sAhH = smem + 2 * AT128;
    char* sAhL = smem + 3 * AT128;
    char* sBH  = smem + 4 * AT128;
    char* sBL  = smem + 5 * AT128;
    const int tid = threadIdx.x, wid = tid >> 5, lane = tid & 31;
    const int wm = wid & 3, wn = wid >> 2;
    const int row0 = blockIdx.x * 128;
    const int y = blockIdx.y;
    const int ck = (y < 2) ? y : 2;

    if (y != 3) tile_async(sAaH, sAaL, g_ah + (size_t)row0 * DD, g_al + (size_t)row0 * DD, tid);
    if (y != 2) tile_async(sAhH, sAhL, g_hh + (size_t)row0 * DD, g_hl + (size_t)row0 * DD, tid);
    if (y == 3) tile_async(sBH, sBL, g_Bhh_hi + 2 * 16384, g_Bhh_lo + 2 * 16384, tid);
    else        tile_async(sBH, sBL, g_Bih_hi + ck * 16384, g_Bih_lo + ck * 16384, tid);
    CP_COMMIT();
    CP_WAIT(0);
    __syncthreads();

    const uint32_t aoff = (uint32_t)((wm * 32 + (lane & 15)) * RB + (lane >> 4) * 16);
    const uint32_t boff = (uint32_t)((wn * 64 + ((lane >> 4) & 1) * 8 + (lane & 7)) * RB
                                     + ((lane >> 3) & 1) * 16);
    float acc[2][8][4];
    zero_acc(acc);

    {
        uint32_t uH = (y == 3) ? smem_u32(sAhH) : smem_u32(sAaH);
        uint32_t uL = (y == 3) ? smem_u32(sAhL) : smem_u32(sAaL);
        mma_accum_3term(acc, uH, uL, smem_u32(sBH), smem_u32(sBL), aoff, boff);
    }
    if (y < 2) {
        __syncthreads();
        tile_async(sBH, sBL, g_Bhh_hi + ck * 16384, g_Bhh_lo + ck * 16384, tid);
        CP_COMMIT();
        CP_WAIT(0);
        __syncthreads();
        mma_accum_3term(acc, smem_u32(sAhH), smem_u32(sAhL),
                        smem_u32(sBH), smem_u32(sBL), aoff, boff);
    }

    float* C = (y == 0) ? g_rs : (y == 1) ? g_zs : (y == 2) ? g_in : g_hn;
#pragma unroll
    for (int mi = 0; mi < 2; mi++) {
        int r0 = row0 + wm * 32 + mi * 16 + (lane >> 2);
#pragma unroll
        for (int n8 = 0; n8 < 8; n8++) {
            int col = wn * 64 + n8 * 8 + (lane & 3) * 2;
            if (r0 < NN)
                *(float2*)(C + (size_t)r0 * DD + col) =
                    make_float2(acc[mi][n8][0], acc[mi][n8][1]);
            if (r0 + 8 < NN)
                *(float2*)(C + (size_t)(r0 + 8) * DD + col) =
                    make_float2(acc[mi][n8][2], acc[mi][n8][3]);
        }
    }
}

// ---------------- GRU pointwise: writes fp32 h + split ------------------
__global__ void gru_kernel(const float* __restrict__ bih, const float* __restrict__ bhh) {
    int idx = blockIdx.x * blockDim.x + threadIdx.x;
    if (idx >= NN * 32) return;
    int n = idx >> 5, q = idx & 31;
    int col = q * 4;
    size_t o = (size_t)n * DD + col;
    float4 rs = *(const float4*)&g_rs[o];
    float4 zs = *(const float4*)&g_zs[o];
    float4 iv = *(const float4*)&g_in[o];
    float4 hv = *(const float4*)&g_hn[o];
    float4 h  = *(const float4*)&g_hf[o];
    float4 br  = *(const float4*)&bih[col];
    float4 br2 = *(const float4*)&bhh[col];
    float4 bz  = *(const float4*)&bih[128 + col];
    float4 bz2 = *(const float4*)&bhh[128 + col];
    float4 bn  = *(const float4*)&bih[256 + col];
    float4 bn2 = *(const float4*)&bhh[256 + col];
    float hin[4] = {h.x, h.y, h.z, h.w};
    float rsv[4] = {rs.x, rs.y, rs.z, rs.w};
    float zsv[4] = {zs.x, zs.y, zs.z, zs.w};
    float ivv[4] = {iv.x, iv.y, iv.z, iv.w};
    float hvv[4] = {hv.x, hv.y, hv.z, hv.w};
    float brv[4] = {br.x + br2.x, br.y + br2.y, br.z + br2.z, br.w + br2.w};
    float bzv[4] = {bz.x + bz2.x, bz.y + bz2.y, bz.z + bz2.z, bz.w + bz2.w};
    float bnv[4] = {bn.x, bn.y, bn.z, bn.w};
    float bn2v[4] = {bn2.x, bn2.y, bn2.z, bn2.w};
    float out[4];
#pragma unroll
    for (int j = 0; j < 4; j++) {
        float r = 1.f / (1.f + expf(-(rsv[j] + brv[j])));
        float z = 1.f / (1.f + expf(-(zsv[j] + bzv[j])));
        float ng = tanhf(ivv[j] + bnv[j] + r * (hvv[j] + bn2v[j]));
        out[j] = (1.f - z) * ng + z * hin[j];
    }
    *(float4*)&g_hf[o] = make_float4(out[0], out[1], out[2], out[3]);
    __nv_bfloat16 oh[4], ol[4];
#pragma unroll
    for (int j = 0; j < 4; j++) split2(out[j], oh[j], ol[j]);
    __nv_bfloat162 ohp0 = {oh[0], oh[1]}, ohp1 = {oh[2], oh[3]};
    __nv_bfloat162 olp0 = {ol[0], ol[1]}, olp1 = {ol[2], ol[3]};
    *(uint2*)(g_hh + o) = make_uint2(*(uint32_t*)&ohp0, *(uint32_t*)&ohp1);
    *(uint2*)(g_hl + o) = make_uint2(*(uint32_t*)&olp0, *(uint32_t*)&olp1);
}

// ---------------- pooling + classifier ----------------
__global__ void zero_feats_kernel() {
    int i = blockIdx.x * blockDim.x + threadIdx.x;
    if (i < BG * DD) g_feats[i] = 0.f;
}
__global__ void pool_kernel(const int* __restrict__ n2g) {
    int n0 = blockIdx.x * 64;
    int j  = threadIdx.x;
    if (n0 >= NN) return;
    float acc = 0.f;
    int cur = n2g[n0];
    for (int i = 0; i < 64; i++) {
        int n = n0 + i;
        if (n >= NN) break;
        int g = n2g[n];
        if (g != cur) {
            atomicAdd(&g_feats[cur * DD + j], acc);
            acc = 0.f; cur = g;
        }
        size_t o = (size_t)n * DD + j;
        acc += g_hf[o] + g_h1[o];
    }
    atomicAdd(&g_feats[cur * DD + j], acc);
}
__global__ void cls_kernel(const float* __restrict__ Wc,
                           const float* __restrict__ bc,
                           float* __restrict__ out) {
    int tid = threadIdx.x;
    if (tid >= BG * 2) return;
    int g = tid >> 1, c = tid & 1;
    float s = bc[c];
#pragma unroll 8
    for (int k = 0; k < DD; k++) s += g_feats[g * DD + k] * Wc[k * 2 + c];
    out[g * 2 + c] = s;
}

// ---------------- launch ----------------
extern "C" void kernel_launch(void* const* d_in, const int* in_sizes, int n_in,
                              void* d_out, int out_size) {
    const float* features = (const float*)d_in[0];
    const int*   src      = (const int*)  d_in[1];
    const int*   dst      = (const int*)  d_in[2];
    const int*   etype    = (const int*)  d_in[3];
    const int*   n2g      = (const int*)  d_in[4];
    const float* W_msg    = (const float*)d_in[5];
    const float* b_msg    = (const float*)d_in[6];
    const float* w_ih     = (const float*)d_in[7];
    const float* b_ih     = (const float*)d_in[8];
    const float* w_hh     = (const float*)d_in[9];
    const float* b_hh     = (const float*)d_in[10];
    const float* W_cls    = (const float*)d_in[11];
    const float* b_cls    = (const float*)d_in[12];
    float* out = (float*)d_out;

    static int inited = 0;
    if (!inited) {
        cudaFuncSetAttribute(msg_kernel,
                             cudaFuncAttributeMaxDynamicSharedMemorySize, SM6);
        cudaFuncSetAttribute(gates_tc,
                             cudaFuncAttributeMaxDynamicSharedMemorySize, SM6);
        inited = 1;
    }

    // prologue — exactly 5 launches so launch #5 is gather_s (profiled)
    fused_prep<<<(NN * DD + 255) / 256, 256>>>(features, W_msg, w_ih, w_hh);
    count_kernel<<<(EE + 255) / 256, 256>>>(dst, etype);
    scan_a_kernel<<<NBS, 1024>>>();
    scan_b_kernel<<<1, 256>>>();
    fill_kernel<<<(EE + 255) / 256, 256>>>(src, dst, etype);

    for (int s = 0; s < NSTEPS; s++) {
        gather_s<<<(NT + 7) / 8, 256>>>();
        msg_kernel<<<RTILES, 256, SM6>>>(b_msg);
        gates_tc<<<dim3(RTILES, 4), 256, SM6>>>();
        gru_kernel<<<(NN * 32 + 255) / 256, 256>>>(b_ih, b_hh);
    }

    zero_feats_kernel<<<(BG * DD + 255) / 256, 256>>>();
    pool_kernel<<<(NN + 63) / 64, 128>>>(n2g);
    cls_kernel<<<1, 128>>>(W_cls, b_cls, out);
}

// round 13
// speedup vs baseline: 1.3645x; 1.3645x over previous
#include <cuda_runtime.h>
#include <cuda_fp16.h>
#include <cstdint>

#define NN 50000
#define EE 400000
#define TT 4
#define DIN 64
#define DD 128
#define BG 64
#define NSTEPS 8
#define RTILES ((NN + 127) / 128)   // 391
#define TPB 37                      // persistent transform blocks per type
#define NB1 ((NN + 255) / 256)      // 196 scan blocks

// ---------------- device scratch ----------------
__device__ float g_h1[NN * DD];                 // residual (fp32)
__device__ float g_hf[NN * DD];                 // current h (fp32 master)
__device__ float g_t [NN * TT * DD];            // messages (fp32)
__device__ float g_rs[NN * DD];
__device__ float g_zs[NN * DD];
__device__ float g_in[NN * DD];
__device__ float g_hn[NN * DD];
__device__ float g_feats[BG * DD];
// fp16 hi/lo state planes (padded one tile for OOB loads)
__device__ __half g_hh[(NN + 128) * DD];
__device__ __half g_hl[(NN + 128) * DD];
__device__ __half g_ah[(NN + 128) * DD];
__device__ __half g_al[(NN + 128) * DD];
// CSR by dst
__device__ int g_cnt [NN];
__device__ int g_scan[NN];
__device__ int g_part [256];
__device__ int g_part2[256];
__device__ int g_eoff[EE];
__device__ int g_gsrc[EE];               // payload: src*512 + etype*128
// fp16 weights, B layout [col][k]
__device__ __half g_Wf  [TT * DD * DD];
__device__ __half g_Bih [3 * DD * DD];
__device__ __half g_Bhh [3 * DD * DD];

// ---------------- helpers ----------------
__device__ __forceinline__ uint32_t smem_u32(const void* p) {
    return (uint32_t)__cvta_generic_to_shared(p);
}
__device__ __forceinline__ void ldsm_x4(uint32_t* r, uint32_t addr) {
    asm volatile("ldmatrix.sync.aligned.m8n8.x4.shared.b16 {%0,%1,%2,%3}, [%4];"
                 : "=r"(r[0]), "=r"(r[1]), "=r"(r[2]), "=r"(r[3]) : "r"(addr));
}
__device__ __forceinline__ void mma16816(float* d, const uint32_t* a, const uint32_t* b) {
    asm volatile(
        "mma.sync.aligned.m16n8k16.row.col.f32.f16.f16.f32 "
        "{%0,%1,%2,%3}, {%4,%5,%6,%7}, {%8,%9}, {%0,%1,%2,%3};"
        : "+f"(d[0]), "+f"(d[1]), "+f"(d[2]), "+f"(d[3])
        : "r"(a[0]), "r"(a[1]), "r"(a[2]), "r"(a[3]), "r"(b[0]), "r"(b[1]));
}
__device__ __forceinline__ void cp16(uint32_t dst, const void* src) {
    asm volatile("cp.async.cg.shared.global [%0], [%1], 16;" :: "r"(dst), "l"(src));
}
#define CP_COMMIT() asm volatile("cp.async.commit_group;" ::: "memory")
#define CP_WAIT(n)  asm volatile("cp.async.wait_group %0;" :: "n"(n) : "memory")

#define TROW 136
#define RB   (TROW * 2)            // 272B row stride
#define AT128 (128 * RB)           // 34816 per fp16 tile
#define SM5   (5 * AT128)          // 174080

// fp16 hi/lo split
__device__ __forceinline__ void split2(float v, __half& h, __half& l) {
    h = __float2half(v);
    l = __float2half(v - __half2float(h));
}

// async copy of one 128x128 fp16 tile, row-major source
__device__ __forceinline__ void tile_async(char* bs, const __half* __restrict__ B, int tid) {
    uint32_t ub = smem_u32(bs);
#pragma unroll
    for (int i = 0; i < 8; i++) {
        int f = tid + 256 * i;
        int r = f >> 4, c8 = (f & 15) * 8;
        cp16(ub + r * RB + c8 * 2, B + (size_t)r * DD + c8);
    }
}

// 2-term fp16 K=128 accumulate: acc += (Ahi + Alo) @ B
__device__ __forceinline__ void mma_accum_2t(float acc[2][8][4],
        uint32_t uAH, uint32_t uAL, uint32_t uB, uint32_t aoff, uint32_t boff) {
#pragma unroll
    for (int t = 0; t < 2; t++) {
        uint32_t ua = (t == 0) ? uAH : uAL;
#pragma unroll
        for (int k = 0; k < 8; k++) {
            uint32_t kb = k * 32;
            uint32_t afr[2][4], bfr[4][4];
            ldsm_x4(afr[0], ua + aoff + kb);
            ldsm_x4(afr[1], ua + aoff + kb + 16 * RB);
#pragma unroll
            for (int ni = 0; ni < 4; ni++)
                ldsm_x4(bfr[ni], uB + boff + kb + ni * 16 * RB);
#pragma unroll
            for (int mi = 0; mi < 2; mi++)
#pragma unroll
                for (int ni = 0; ni < 4; ni++) {
                    mma16816(acc[mi][ni * 2 + 0], afr[mi], &bfr[ni][0]);
                    mma16816(acc[mi][ni * 2 + 1], afr[mi], &bfr[ni][2]);
                }
        }
    }
}
__device__ __forceinline__ void zero_acc(float acc[2][8][4]) {
#pragma unroll
    for (int mi = 0; mi < 2; mi++)
#pragma unroll
        for (int n8 = 0; n8 < 8; n8++)
#pragma unroll
            for (int j = 0; j < 4; j++) acc[mi][n8][j] = 0.f;
}

// ---------------- transform: persistent, grid (37, 4) -------------------
// g_t[:, tt*128:+128] = h @ Wmsg[tt]^T + bmsg[tt]; A-pair double-buffered
__global__ __launch_bounds__(256) void transform_tc(const float* __restrict__ bias) {
    extern __shared__ char smem[];
    char* sA[2][2] = {{smem, smem + AT128},
                      {smem + 2 * AT128, smem + 3 * AT128}};
    char* sB = smem + 4 * AT128;
    const int tid = threadIdx.x, wid = tid >> 5, lane = tid & 31;
    const int wm = wid & 3, wn = wid >> 2;
    const int x = blockIdx.x, tt = blockIdx.y;

    tile_async(sB, g_Wf + tt * 16384, tid);
    tile_async(sA[0][0], g_hh + (size_t)x * 128 * DD, tid);
    tile_async(sA[0][1], g_hl + (size_t)x * 128 * DD, tid);
    CP_COMMIT();

    const uint32_t aoff = (uint32_t)((wm * 32 + (lane & 15)) * RB + (lane >> 4) * 16);
    const uint32_t boff = (uint32_t)((wn * 64 + ((lane >> 4) & 1) * 8 + (lane & 7)) * RB
                                     + ((lane >> 3) & 1) * 16);
    const uint32_t uB = smem_u32(sB);
    const uint32_t uA[2][2] = {{smem_u32(sA[0][0]), smem_u32(sA[0][1])},
                               {smem_u32(sA[1][0]), smem_u32(sA[1][1])}};

    int buf = 0;
    for (int ti = x; ti < RTILES; ti += TPB) {
        int tn = ti + TPB;
        if (tn < RTILES) {
            tile_async(sA[buf ^ 1][0], g_hh + (size_t)tn * 128 * DD, tid);
            tile_async(sA[buf ^ 1][1], g_hl + (size_t)tn * 128 * DD, tid);
            CP_COMMIT();
            CP_WAIT(1);
        } else {
            CP_WAIT(0);
        }
        __syncthreads();

        float acc[2][8][4];
        zero_acc(acc);
        mma_accum_2t(acc, uA[buf][0], uA[buf][1], uB, aoff, boff);

        int row0 = ti * 128;
#pragma unroll
        for (int mi = 0; mi < 2; mi++) {
            int r0 = row0 + wm * 32 + mi * 16 + (lane >> 2);
#pragma unroll
            for (int n8 = 0; n8 < 8; n8++) {
                int col = wn * 64 + n8 * 8 + (lane & 3) * 2;
                float b0 = bias[tt * 128 + col], b1 = bias[tt * 128 + col + 1];
                if (r0 < NN)
                    *(float2*)(g_t + (size_t)r0 * 512 + tt * 128 + col) =
                        make_float2(acc[mi][n8][0] + b0, acc[mi][n8][1] + b1);
                if (r0 + 8 < NN)
                    *(float2*)(g_t + (size_t)(r0 + 8) * 512 + tt * 128 + col) =
                        make_float2(acc[mi][n8][2] + b0, acc[mi][n8][3] + b1);
            }
        }
        __syncthreads();
        buf ^= 1;
    }
}

// ---------------- gates: grid (391, 4) ----------------------------------
// y=0: rs = a@ih_r + h@hh_r ; y=1: zs ; y=2: in = a@ih_n ; y=3: hn = h@hh_n
__global__ __launch_bounds__(256) void gates_tc() {
    extern __shared__ char smem[];
    char* sAaH = smem;
    char* sAaL = smem + AT128;
    char* sAhH = smem + 2 * AT128;
    char* sAhL = smem + 3 * AT128;
    char* sB   = smem + 4 * AT128;
    const int tid = threadIdx.x, wid = tid >> 5, lane = tid & 31;
    const int wm = wid & 3, wn = wid >> 2;
    const int row0 = blockIdx.x * 128;
    const int y = blockIdx.y;
    const int ck = (y < 2) ? y : 2;

    if (y != 3) {
        tile_async(sAaH, g_ah + (size_t)row0 * DD, tid);
        tile_async(sAaL, g_al + (size_t)row0 * DD, tid);
    }
    if (y != 2) {
        tile_async(sAhH, g_hh + (size_t)row0 * DD, tid);
        tile_async(sAhL, g_hl + (size_t)row0 * DD, tid);
    }
    if (y == 3) tile_async(sB, g_Bhh + 2 * 16384, tid);
    else        tile_async(sB, g_Bih + ck * 16384, tid);
    CP_COMMIT();
    CP_WAIT(0);
    __syncthreads();

    const uint32_t aoff = (uint32_t)((wm * 32 + (lane & 15)) * RB + (lane >> 4) * 16);
    const uint32_t boff = (uint32_t)((wn * 64 + ((lane >> 4) & 1) * 8 + (lane & 7)) * RB
                                     + ((lane >> 3) & 1) * 16);
    float acc[2][8][4];
    zero_acc(acc);

    {   // pass 1: A = a (y=0,1,2) or h (y=3)
        uint32_t uH = (y == 3) ? smem_u32(sAhH) : smem_u32(sAaH);
        uint32_t uL = (y == 3) ? smem_u32(sAhL) : smem_u32(sAaL);
        mma_accum_2t(acc, uH, uL, smem_u32(sB), aoff, boff);
    }
    if (y < 2) {  // pass 2: + h @ hh_ck
        __syncthreads();
        tile_async(sB, g_Bhh + ck * 16384, tid);
        CP_COMMIT();
        CP_WAIT(0);
        __syncthreads();
        mma_accum_2t(acc, smem_u32(sAhH), smem_u32(sAhL), smem_u32(sB), aoff, boff);
    }

    float* C = (y == 0) ? g_rs : (y == 1) ? g_zs : (y == 2) ? g_in : g_hn;
#pragma unroll
    for (int mi = 0; mi < 2; mi++) {
        int r0 = row0 + wm * 32 + mi * 16 + (lane >> 2);
#pragma unroll
        for (int n8 = 0; n8 < 8; n8++) {
            int col = wn * 64 + n8 * 8 + (lane & 3) * 2;
            if (r0 < NN)
                *(float2*)(C + (size_t)r0 * DD + col) =
                    make_float2(acc[mi][n8][0], acc[mi][n8][1]);
            if (r0 + 8 < NN)
                *(float2*)(C + (size_t)(r0 + 8) * DD + col) =
                    make_float2(acc[mi][n8][2], acc[mi][n8][3]);
        }
    }
}

// ---------------- fused prologue prep (launch 0) ----------------
__global__ void fused_prep(const float* __restrict__ features,
                           const float* __restrict__ Wmsg,
                           const float* __restrict__ wih,
                           const float* __restrict__ whh) {
    int idx = blockIdx.x * blockDim.x + threadIdx.x;
    if (idx < TT * DD * DD) {
        int t = idx >> 14, rem = idx & 16383, e = rem >> 7, d = rem & 127;
        g_Wf[idx] = __float2half(Wmsg[t * 16384 + d * 128 + e]);
    }
    if (idx < 3 * DD * DD) {
        int c = idx >> 7, k = idx & 127;
        g_Bih[idx] = __float2half(wih[k * 384 + c]);
        g_Bhh[idx] = __float2half(whh[k * 384 + c]);
    }
    if (idx < NN) g_cnt[idx] = 0;
    if (idx < NN * DD) {
        int n = idx >> 7, j = idx & 127;
        float v = (j < DIN) ? features[n * DIN + j] : 0.f;
        g_h1[idx] = v;
        g_hf[idx] = v;
        __half hi, lo;
        split2(v, hi, lo);
        g_hh[idx] = hi;
        g_hl[idx] = lo;
    }
}

// ---------------- CSR build (by dst) ----------------
__global__ void count_kernel(const int* __restrict__ dst) {
    int e = blockIdx.x * blockDim.x + threadIdx.x;
    if (e >= EE) return;
    g_eoff[e] = atomicAdd(&g_cnt[dst[e]], 1);
}
__global__ void scan_a_kernel() {
    __shared__ int s[256];
    int b = blockIdx.x, t = threadIdx.x;
    int n = b * 256 + t;
    int v = (n < NN) ? g_cnt[n] : 0;
    s[t] = v;
    __syncthreads();
    for (int d = 1; d < 256; d <<= 1) {
        int x = (t >= d) ? s[t - d] : 0;
        __syncthreads();
        s[t] += x;
        __syncthreads();
    }
    if (n < NN) g_scan[n] = s[t] - v;
    if (t == 255) g_part[b] = s[255];
}
__global__ void scan_b_kernel() {
    __shared__ int s[256];
    int t = threadIdx.x;
    int v = (t < NB1) ? g_part[t] : 0;
    s[t] = v;
    __syncthreads();
    for (int d = 1; d < 256; d <<= 1) {
        int x = (t >= d) ? s[t - d] : 0;
        __syncthreads();
        s[t] += x;
        __syncthreads();
    }
    g_part2[t] = s[t] - v;
}
__global__ void fill_kernel(const int* __restrict__ src, const int* __restrict__ dst,
                            const int* __restrict__ et) {
    int e = blockIdx.x * blockDim.x + threadIdx.x;
    if (e >= EE) return;
    int b = dst[e];
    int pos = g_scan[b] + g_part2[b >> 8] + g_eoff[e];
    g_gsrc[pos] = src[e] * 512 + et[e] * 128;
}

// ---------------- gather: a[d] = sum msgs; writes split fp16 ------------
__global__ __launch_bounds__(256) void gather_kernel() {
    int w = blockIdx.x * 8 + (threadIdx.x >> 5);
    if (w >= NN) return;
    int lane = threadIdx.x & 31;
    int lo = g_scan[w] + g_part2[w >> 8];
    int hi = (w == NN - 1) ? EE : (g_scan[w + 1] + g_part2[(w + 1) >> 8]);
    float4 a0 = make_float4(0.f, 0.f, 0.f, 0.f);
    float4 a1 = make_float4(0.f, 0.f, 0.f, 0.f);
    int i = lo;
    for (; i + 1 < hi; i += 2) {
        int s0 = g_gsrc[i], s1 = g_gsrc[i + 1];
        float4 v0 = *(const float4*)&g_t[s0 + lane * 4];
        float4 v1 = *(const float4*)&g_t[s1 + lane * 4];
        a0.x += v0.x; a0.y += v0.y; a0.z += v0.z; a0.w += v0.w;
        a1.x += v1.x; a1.y += v1.y; a1.z += v1.z; a1.w += v1.w;
    }
    if (i < hi) {
        int s0 = g_gsrc[i];
        float4 v0 = *(const float4*)&g_t[s0 + lane * 4];
        a0.x += v0.x; a0.y += v0.y; a0.z += v0.z; a0.w += v0.w;
    }
    a0.x += a1.x; a0.y += a1.y; a0.z += a1.z; a0.w += a1.w;

    __half h0, l0, h1, l1, h2, l2, h3, l3;
    split2(a0.x, h0, l0); split2(a0.y, h1, l1);
    split2(a0.z, h2, l2); split2(a0.w, h3, l3);
    __half2 hp0 = {h0, h1}, hp1 = {h2, h3};
    __half2 lp0 = {l0, l1}, lp1 = {l2, l3};
    size_t o = (size_t)w * DD + lane * 4;
    *(uint2*)(g_ah + o) = make_uint2(*(uint32_t*)&hp0, *(uint32_t*)&hp1);
    *(uint2*)(g_al + o) = make_uint2(*(uint32_t*)&lp0, *(uint32_t*)&lp1);
}

// ---------------- GRU pointwise: writes fp32 + split fp16 h -------------
__global__ void gru_kernel(const float* __restrict__ bih, const float* __restrict__ bhh) {
    int idx = blockIdx.x * blockDim.x + threadIdx.x;
    if (idx >= NN * 32) return;
    int n = idx >> 5, q = idx & 31;
    int col = q * 4;
    size_t o = (size_t)n * DD + col;
    float4 rs = *(const float4*)&g_rs[o];
    float4 zs = *(const float4*)&g_zs[o];
    float4 iv = *(const float4*)&g_in[o];
    float4 hv = *(const float4*)&g_hn[o];
    float4 h  = *(const float4*)&g_hf[o];
    float4 br  = *(const float4*)&bih[col];
    float4 br2 = *(const float4*)&bhh[col];
    float4 bz  = *(const float4*)&bih[128 + col];
    float4 bz2 = *(const float4*)&bhh[128 + col];
    float4 bn  = *(const float4*)&bih[256 + col];
    float4 bn2 = *(const float4*)&bhh[256 + col];
    float hin[4] = {h.x, h.y, h.z, h.w};
    float rsv[4] = {rs.x, rs.y, rs.z, rs.w};
    float zsv[4] = {zs.x, zs.y, zs.z, zs.w};
    float ivv[4] = {iv.x, iv.y, iv.z, iv.w};
    float hvv[4] = {hv.x, hv.y, hv.z, hv.w};
    float brv[4] = {br.x + br2.x, br.y + br2.y, br.z + br2.z, br.w + br2.w};
    float bzv[4] = {bz.x + bz2.x, bz.y + bz2.y, bz.z + bz2.z, bz.w + bz2.w};
    float bnv[4] = {bn.x, bn.y, bn.z, bn.w};
    float bn2v[4] = {bn2.x, bn2.y, bn2.z, bn2.w};
    float out[4];
#pragma unroll
    for (int j = 0; j < 4; j++) {
        float r = 1.f / (1.f + expf(-(rsv[j] + brv[j])));
        float z = 1.f / (1.f + expf(-(zsv[j] + bzv[j])));
        float ng = tanhf(ivv[j] + bnv[j] + r * (hvv[j] + bn2v[j]));
        out[j] = (1.f - z) * ng + z * hin[j];
    }
    *(float4*)&g_hf[o] = make_float4(out[0], out[1], out[2], out[3]);
    __half oh[4], ol[4];
#pragma unroll
    for (int j = 0; j < 4; j++) split2(out[j], oh[j], ol[j]);
    __half2 hp0 = {oh[0], oh[1]}, hp1 = {oh[2], oh[3]};
    __half2 lp0 = {ol[0], ol[1]}, lp1 = {ol[2], ol[3]};
    *(uint2*)(g_hh + o) = make_uint2(*(uint32_t*)&hp0, *(uint32_t*)&hp1);
    *(uint2*)(g_hl + o) = make_uint2(*(uint32_t*)&lp0, *(uint32_t*)&lp1);
}

// ---------------- pooling + classifier ----------------
__global__ void zero_feats_kernel() {
    int i = blockIdx.x * blockDim.x + threadIdx.x;
    if (i < BG * DD) g_feats[i] = 0.f;
}
__global__ void pool_kernel(const int* __restrict__ n2g) {
    int n0 = blockIdx.x * 64;
    int j  = threadIdx.x;
    if (n0 >= NN) return;
    float acc = 0.f;
    int cur = n2g[n0];
    for (int i = 0; i < 64; i++) {
        int n = n0 + i;
        if (n >= NN) break;
        int g = n2g[n];
        if (g != cur) {
            atomicAdd(&g_feats[cur * DD + j], acc);
            acc = 0.f; cur = g;
        }
        size_t o = (size_t)n * DD + j;
        acc += g_hf[o] + g_h1[o];
    }
    atomicAdd(&g_feats[cur * DD + j], acc);
}
__global__ void cls_kernel(const float* __restrict__ Wc,
                           const float* __restrict__ bc,
                           float* __restrict__ out) {
    int tid = threadIdx.x;
    if (tid >= BG * 2) return;
    int g = tid >> 1, c = tid & 1;
    float s = bc[c];
#pragma unroll 8
    for (int k = 0; k < DD; k++) s += g_feats[g * DD + k] * Wc[k * 2 + c];
    out[g * 2 + c] = s;
}

// ---------------- launch ----------------
extern "C" void kernel_launch(void* const* d_in, const int* in_sizes, int n_in,
                              void* d_out, int out_size) {
    const float* features = (const float*)d_in[0];
    const int*   src      = (const int*)  d_in[1];
    const int*   dst      = (const int*)  d_in[2];
    const int*   etype    = (const int*)  d_in[3];
    const int*   n2g      = (const int*)  d_in[4];
    const float* W_msg    = (const float*)d_in[5];
    const float* b_msg    = (const float*)d_in[6];
    const float* w_ih     = (const float*)d_in[7];
    const float* b_ih     = (const float*)d_in[8];
    const float* w_hh     = (const float*)d_in[9];
    const float* b_hh     = (const float*)d_in[10];
    const float* W_cls    = (const float*)d_in[11];
    const float* b_cls    = (const float*)d_in[12];
    float* out = (float*)d_out;

    static int inited = 0;
    if (!inited) {
        cudaFuncSetAttribute(transform_tc,
                             cudaFuncAttributeMaxDynamicSharedMemorySize, SM5);
        cudaFuncSetAttribute(gates_tc,
                             cudaFuncAttributeMaxDynamicSharedMemorySize, SM5);
        inited = 1;
    }

    // prologue — 5 launches
    fused_prep<<<(NN * DD + 255) / 256, 256>>>(features, W_msg, w_ih, w_hh);
    count_kernel<<<(EE + 255) / 256, 256>>>(dst);
    scan_a_kernel<<<NB1, 256>>>();
    scan_b_kernel<<<1, 256>>>();
    fill_kernel<<<(EE + 255) / 256, 256>>>(src, dst, etype);

    for (int s = 0; s < NSTEPS; s++) {
        transform_tc<<<dim3(TPB, TT), 256, SM5>>>(b_msg);
        gather_kernel<<<(NN + 7) / 8, 256>>>();
        gates_tc<<<dim3(RTILES, 4), 256, SM5>>>();
        gru_kernel<<<(NN * 32 + 255) / 256, 256>>>(b_ih, b_hh);
    }

    zero_feats_kernel<<<(BG * DD + 255) / 256, 256>>>();
    pool_kernel<<<(NN + 63) / 64, 128>>>(n2g);
    cls_kernel<<<1, 128>>>(W_cls, b_cls, out);
}

// round 14
// speedup vs baseline: 1.6272x; 1.1925x over previous
#include <cuda_runtime.h>
#include <cuda_fp16.h>
#include <cstdint>

#define NN 50000
#define EE 400000
#define TT 4
#define DIN 64
#define DD 128
#define BG 64
#define NSTEPS 8
#define RTILES ((NN + 127) / 128)   // 391
#define TPB 37                      // persistent transform blocks per type
#define NB1 ((NN + 255) / 256)      // 196 scan blocks

// ---------------- device scratch ----------------
__device__ float g_h1[NN * DD];                 // residual (fp32)
__device__ float g_hf[NN * DD];                 // current h (fp32 master)
__device__ __half g_t [NN * TT * DD];           // messages (fp16)
__device__ float g_rs[NN * DD];
__device__ float g_zs[NN * DD];
__device__ float g_in[NN * DD];
__device__ float g_hn[NN * DD];
__device__ float g_feats[BG * DD];
// single-fp16 state planes (padded one tile for OOB loads)
__device__ __half g_hh[(NN + 128) * DD];
__device__ __half g_ah[(NN + 128) * DD];
// CSR by dst
__device__ int g_cnt [NN];
__device__ int g_scan[NN];
__device__ int g_part [256];
__device__ int g_part2[256];
__device__ int g_eoff[EE];
__device__ int g_gsrc[EE];               // payload: src*512 + etype*128
// fp16 hi/lo weights, B layout [col][k]
__device__ __half g_WfH [TT * DD * DD];
__device__ __half g_WfL [TT * DD * DD];
__device__ __half g_BihH[3 * DD * DD];
__device__ __half g_BihL[3 * DD * DD];
__device__ __half g_BhhH[3 * DD * DD];
__device__ __half g_BhhL[3 * DD * DD];

// ---------------- helpers ----------------
__device__ __forceinline__ uint32_t smem_u32(const void* p) {
    return (uint32_t)__cvta_generic_to_shared(p);
}
__device__ __forceinline__ void ldsm_x4(uint32_t* r, uint32_t addr) {
    asm volatile("ldmatrix.sync.aligned.m8n8.x4.shared.b16 {%0,%1,%2,%3}, [%4];"
                 : "=r"(r[0]), "=r"(r[1]), "=r"(r[2]), "=r"(r[3]) : "r"(addr));
}
__device__ __forceinline__ void mma16816(float* d, const uint32_t* a, const uint32_t* b) {
    asm volatile(
        "mma.sync.aligned.m16n8k16.row.col.f32.f16.f16.f32 "
        "{%0,%1,%2,%3}, {%4,%5,%6,%7}, {%8,%9}, {%0,%1,%2,%3};"
        : "+f"(d[0]), "+f"(d[1]), "+f"(d[2]), "+f"(d[3])
        : "r"(a[0]), "r"(a[1]), "r"(a[2]), "r"(a[3]), "r"(b[0]), "r"(b[1]));
}
__device__ __forceinline__ void cp16(uint32_t dst, const void* src) {
    asm volatile("cp.async.cg.shared.global [%0], [%1], 16;" :: "r"(dst), "l"(src));
}
#define CP_COMMIT() asm volatile("cp.async.commit_group;" ::: "memory")
#define CP_WAIT(n)  asm volatile("cp.async.wait_group %0;" :: "n"(n) : "memory")

#define TROW 136
#define RB   (TROW * 2)            // 272B row stride
#define AT128 (128 * RB)           // 34816 per fp16 tile
#define SM4   (4 * AT128)          // 139264

// fp16 hi/lo split
__device__ __forceinline__ void split2(float v, __half& h, __half& l) {
    h = __float2half(v);
    l = __float2half(v - __half2float(h));
}

// async copy of one 128x128 fp16 tile, row-major source
__device__ __forceinline__ void tile_async(char* bs, const __half* __restrict__ B, int tid) {
    uint32_t ub = smem_u32(bs);
#pragma unroll
    for (int i = 0; i < 8; i++) {
        int f = tid + 256 * i;
        int r = f >> 4, c8 = (f & 15) * 8;
        cp16(ub + r * RB + c8 * 2, B + (size_t)r * DD + c8);
    }
}

// 2-term fp16 K=128 accumulate: acc += A @ (Bhi + Blo)
__device__ __forceinline__ void mma_accum_2t(float acc[2][8][4],
        uint32_t uA, uint32_t uBH, uint32_t uBL, uint32_t aoff, uint32_t boff) {
#pragma unroll
    for (int k = 0; k < 8; k++) {
        uint32_t kb = k * 32;
        uint32_t afr[2][4];
        ldsm_x4(afr[0], uA + aoff + kb);
        ldsm_x4(afr[1], uA + aoff + kb + 16 * RB);
#pragma unroll
        for (int t = 0; t < 2; t++) {
            uint32_t ub = (t == 0) ? uBH : uBL;
            uint32_t bfr[4][4];
#pragma unroll
            for (int ni = 0; ni < 4; ni++)
                ldsm_x4(bfr[ni], ub + boff + kb + ni * 16 * RB);
#pragma unroll
            for (int mi = 0; mi < 2; mi++)
#pragma unroll
                for (int ni = 0; ni < 4; ni++) {
                    mma16816(acc[mi][ni * 2 + 0], afr[mi], &bfr[ni][0]);
                    mma16816(acc[mi][ni * 2 + 1], afr[mi], &bfr[ni][2]);
                }
        }
    }
}
__device__ __forceinline__ void zero_acc(float acc[2][8][4]) {
#pragma unroll
    for (int mi = 0; mi < 2; mi++)
#pragma unroll
        for (int n8 = 0; n8 < 8; n8++)
#pragma unroll
            for (int j = 0; j < 4; j++) acc[mi][n8][j] = 0.f;
}

// ---------------- transform: persistent, grid (37, 4) -------------------
// g_t[:, tt*128:+128] = fp16( h @ Wmsg[tt]^T + bmsg[tt] ); A double-buffered
__global__ __launch_bounds__(256) void transform_tc(const float* __restrict__ bias) {
    extern __shared__ char smem[];
    char* sA0 = smem;
    char* sA1 = smem + AT128;
    char* sBH = smem + 2 * AT128;
    char* sBL = smem + 3 * AT128;
    const int tid = threadIdx.x, wid = tid >> 5, lane = tid & 31;
    const int wm = wid & 3, wn = wid >> 2;
    const int x = blockIdx.x, tt = blockIdx.y;

    tile_async(sBH, g_WfH + tt * 16384, tid);
    tile_async(sBL, g_WfL + tt * 16384, tid);
    tile_async(sA0, g_hh + (size_t)x * 128 * DD, tid);
    CP_COMMIT();

    const uint32_t aoff = (uint32_t)((wm * 32 + (lane & 15)) * RB + (lane >> 4) * 16);
    const uint32_t boff = (uint32_t)((wn * 64 + ((lane >> 4) & 1) * 8 + (lane & 7)) * RB
                                     + ((lane >> 3) & 1) * 16);
    const uint32_t uBH = smem_u32(sBH), uBL = smem_u32(sBL);
    const uint32_t uA[2] = {smem_u32(sA0), smem_u32(sA1)};
    char* pA[2] = {sA0, sA1};

    int buf = 0;
    for (int ti = x; ti < RTILES; ti += TPB) {
        int tn = ti + TPB;
        if (tn < RTILES) {
            tile_async(pA[buf ^ 1], g_hh + (size_t)tn * 128 * DD, tid);
            CP_COMMIT();
            CP_WAIT(1);
        } else {
            CP_WAIT(0);
        }
        __syncthreads();

        float acc[2][8][4];
        zero_acc(acc);
        mma_accum_2t(acc, uA[buf], uBH, uBL, aoff, boff);

        int row0 = ti * 128;
#pragma unroll
        for (int mi = 0; mi < 2; mi++) {
            int r0 = row0 + wm * 32 + mi * 16 + (lane >> 2);
#pragma unroll
            for (int n8 = 0; n8 < 8; n8++) {
                int col = wn * 64 + n8 * 8 + (lane & 3) * 2;
                float b0 = bias[tt * 128 + col], b1 = bias[tt * 128 + col + 1];
                if (r0 < NN) {
                    __half2 p = __floats2half2_rn(acc[mi][n8][0] + b0, acc[mi][n8][1] + b1);
                    *(__half2*)(g_t + (size_t)r0 * 512 + tt * 128 + col) = p;
                }
                if (r0 + 8 < NN) {
                    __half2 p = __floats2half2_rn(acc[mi][n8][2] + b0, acc[mi][n8][3] + b1);
                    *(__half2*)(g_t + (size_t)(r0 + 8) * 512 + tt * 128 + col) = p;
                }
            }
        }
        __syncthreads();
        buf ^= 1;
    }
}

// ---------------- gates: grid (391, 4) ----------------------------------
// y=0: rs = a@ih_r + h@hh_r ; y=1: zs ; y=2: in = a@ih_n ; y=3: hn = h@hh_n
__global__ __launch_bounds__(256) void gates_tc() {
    extern __shared__ char smem[];
    char* sAa = smem;
    char* sAh = smem + AT128;
    char* sBH = smem + 2 * AT128;
    char* sBL = smem + 3 * AT128;
    const int tid = threadIdx.x, wid = tid >> 5, lane = tid & 31;
    const int wm = wid & 3, wn = wid >> 2;
    const int row0 = blockIdx.x * 128;
    const int y = blockIdx.y;
    const int ck = (y < 2) ? y : 2;

    if (y != 3) tile_async(sAa, g_ah + (size_t)row0 * DD, tid);
    if (y != 2) tile_async(sAh, g_hh + (size_t)row0 * DD, tid);
    if (y == 3) {
        tile_async(sBH, g_BhhH + 2 * 16384, tid);
        tile_async(sBL, g_BhhL + 2 * 16384, tid);
    } else {
        tile_async(sBH, g_BihH + ck * 16384, tid);
        tile_async(sBL, g_BihL + ck * 16384, tid);
    }
    CP_COMMIT();
    CP_WAIT(0);
    __syncthreads();

    const uint32_t aoff = (uint32_t)((wm * 32 + (lane & 15)) * RB + (lane >> 4) * 16);
    const uint32_t boff = (uint32_t)((wn * 64 + ((lane >> 4) & 1) * 8 + (lane & 7)) * RB
                                     + ((lane >> 3) & 1) * 16);
    float acc[2][8][4];
    zero_acc(acc);

    {   // pass 1: A = a (y=0,1,2) or h (y=3)
        uint32_t uA = (y == 3) ? smem_u32(sAh) : smem_u32(sAa);
        mma_accum_2t(acc, uA, smem_u32(sBH), smem_u32(sBL), aoff, boff);
    }
    if (y < 2) {  // pass 2: + h @ hh_ck
        __syncthreads();
        tile_async(sBH, g_BhhH + ck * 16384, tid);
        tile_async(sBL, g_BhhL + ck * 16384, tid);
        CP_COMMIT();
        CP_WAIT(0);
        __syncthreads();
        mma_accum_2t(acc, smem_u32(sAh), smem_u32(sBH), smem_u32(sBL), aoff, boff);
    }

    float* C = (y == 0) ? g_rs : (y == 1) ? g_zs : (y == 2) ? g_in : g_hn;
#pragma unroll
    for (int mi = 0; mi < 2; mi++) {
        int r0 = row0 + wm * 32 + mi * 16 + (lane >> 2);
#pragma unroll
        for (int n8 = 0; n8 < 8; n8++) {
            int col = wn * 64 + n8 * 8 + (lane & 3) * 2;
            if (r0 < NN)
                *(float2*)(C + (size_t)r0 * DD + col) =
                    make_float2(acc[mi][n8][0], acc[mi][n8][1]);
            if (r0 + 8 < NN)
                *(float2*)(C + (size_t)(r0 + 8) * DD + col) =
                    make_float2(acc[mi][n8][2], acc[mi][n8][3]);
        }
    }
}

// ---------------- fused prologue prep (launch 0) ----------------
__global__ void fused_prep(const float* __restrict__ features,
                           const float* __restrict__ Wmsg,
                           const float* __restrict__ wih,
                           const float* __restrict__ whh) {
    int idx = blockIdx.x * blockDim.x + threadIdx.x;
    if (idx < TT * DD * DD) {
        int t = idx >> 14, rem = idx & 16383, e = rem >> 7, d = rem & 127;
        __half hi, lo;
        split2(Wmsg[t * 16384 + d * 128 + e], hi, lo);
        g_WfH[idx] = hi; g_WfL[idx] = lo;
    }
    if (idx < 3 * DD * DD) {
        int c = idx >> 7, k = idx & 127;
        __half hi, lo;
        split2(wih[k * 384 + c], hi, lo);
        g_BihH[idx] = hi; g_BihL[idx] = lo;
        split2(whh[k * 384 + c], hi, lo);
        g_BhhH[idx] = hi; g_BhhL[idx] = lo;
    }
    if (idx < NN) g_cnt[idx] = 0;
    if (idx < NN * DD) {
        int n = idx >> 7, j = idx & 127;
        float v = (j < DIN) ? features[n * DIN + j] : 0.f;
        g_h1[idx] = v;
        g_hf[idx] = v;
        g_hh[idx] = __float2half(v);
    }
}

// ---------------- CSR build (by dst) ----------------
__global__ void count_kernel(const int* __restrict__ dst) {
    int e = blockIdx.x * blockDim.x + threadIdx.x;
    if (e >= EE) return;
    g_eoff[e] = atomicAdd(&g_cnt[dst[e]], 1);
}
__global__ void scan_a_kernel() {
    __shared__ int s[256];
    int b = blockIdx.x, t = threadIdx.x;
    int n = b * 256 + t;
    int v = (n < NN) ? g_cnt[n] : 0;
    s[t] = v;
    __syncthreads();
    for (int d = 1; d < 256; d <<= 1) {
        int x = (t >= d) ? s[t - d] : 0;
        __syncthreads();
        s[t] += x;
        __syncthreads();
    }
    if (n < NN) g_scan[n] = s[t] - v;
    if (t == 255) g_part[b] = s[255];
}
__global__ void scan_b_kernel() {
    __shared__ int s[256];
    int t = threadIdx.x;
    int v = (t < NB1) ? g_part[t] : 0;
    s[t] = v;
    __syncthreads();
    for (int d = 1; d < 256; d <<= 1) {
        int x = (t >= d) ? s[t - d] : 0;
        __syncthreads();
        s[t] += x;
        __syncthreads();
    }
    g_part2[t] = s[t] - v;
}
__global__ void fill_kernel(const int* __restrict__ src, const int* __restrict__ dst,
                            const int* __restrict__ et) {
    int e = blockIdx.x * blockDim.x + threadIdx.x;
    if (e >= EE) return;
    int b = dst[e];
    int pos = g_scan[b] + g_part2[b >> 8] + g_eoff[e];
    g_gsrc[pos] = src[e] * 512 + et[e] * 128;
}

// ---------------- gather: a[d] = sum fp16 msgs; writes fp16 -------------
__global__ __launch_bounds__(256) void gather_kernel() {
    int w = blockIdx.x * 8 + (threadIdx.x >> 5);
    if (w >= NN) return;
    int lane = threadIdx.x & 31;
    int lo = g_scan[w] + g_part2[w >> 8];
    int hi = (w == NN - 1) ? EE : (g_scan[w + 1] + g_part2[(w + 1) >> 8]);
    float4 a0 = make_float4(0.f, 0.f, 0.f, 0.f);
    float4 a1 = make_float4(0.f, 0.f, 0.f, 0.f);
    int i = lo;
    for (; i + 1 < hi; i += 2) {
        int s0 = g_gsrc[i], s1 = g_gsrc[i + 1];
        uint2 u0 = *(const uint2*)(g_t + s0 + lane * 4);
        uint2 u1 = *(const uint2*)(g_t + s1 + lane * 4);
        float2 p00 = __half22float2(*(__half2*)&u0.x);
        float2 p01 = __half22float2(*(__half2*)&u0.y);
        float2 p10 = __half22float2(*(__half2*)&u1.x);
        float2 p11 = __half22float2(*(__half2*)&u1.y);
        a0.x += p00.x; a0.y += p00.y; a0.z += p01.x; a0.w += p01.y;
        a1.x += p10.x; a1.y += p10.y; a1.z += p11.x; a1.w += p11.y;
    }
    if (i < hi) {
        int s0 = g_gsrc[i];
        uint2 u0 = *(const uint2*)(g_t + s0 + lane * 4);
        float2 p00 = __half22float2(*(__half2*)&u0.x);
        float2 p01 = __half22float2(*(__half2*)&u0.y);
        a0.x += p00.x; a0.y += p00.y; a0.z += p01.x; a0.w += p01.y;
    }
    a0.x += a1.x; a0.y += a1.y; a0.z += a1.z; a0.w += a1.w;

    __half2 p0 = __floats2half2_rn(a0.x, a0.y);
    __half2 p1 = __floats2half2_rn(a0.z, a0.w);
    size_t o = (size_t)w * DD + lane * 4;
    *(uint2*)(g_ah + o) = make_uint2(*(uint32_t*)&p0, *(uint32_t*)&p1);
}

// ---------------- GRU pointwise: writes fp32 + fp16 h -------------------
__global__ void gru_kernel(const float* __restrict__ bih, const float* __restrict__ bhh) {
    int idx = blockIdx.x * blockDim.x + threadIdx.x;
    if (idx >= NN * 32) return;
    int n = idx >> 5, q = idx & 31;
    int col = q * 4;
    size_t o = (size_t)n * DD + col;
    float4 rs = *(const float4*)&g_rs[o];
    float4 zs = *(const float4*)&g_zs[o];
    float4 iv = *(const float4*)&g_in[o];
    float4 hv = *(const float4*)&g_hn[o];
    float4 h  = *(const float4*)&g_hf[o];
    float4 br  = *(const float4*)&bih[col];
    float4 br2 = *(const float4*)&bhh[col];
    float4 bz  = *(const float4*)&bih[128 + col];
    float4 bz2 = *(const float4*)&bhh[128 + col];
    float4 bn  = *(const float4*)&bih[256 + col];
    float4 bn2 = *(const float4*)&bhh[256 + col];
    float hin[4] = {h.x, h.y, h.z, h.w};
    float rsv[4] = {rs.x, rs.y, rs.z, rs.w};
    float zsv[4] = {zs.x, zs.y, zs.z, zs.w};
    float ivv[4] = {iv.x, iv.y, iv.z, iv.w};
    float hvv[4] = {hv.x, hv.y, hv.z, hv.w};
    float brv[4] = {br.x + br2.x, br.y + br2.y, br.z + br2.z, br.w + br2.w};
    float bzv[4] = {bz.x + bz2.x, bz.y + bz2.y, bz.z + bz2.z, bz.w + bz2.w};
    float bnv[4] = {bn.x, bn.y, bn.z, bn.w};
    float bn2v[4] = {bn2.x, bn2.y, bn2.z, bn2.w};
    float out[4];
#pragma unroll
    for (int j = 0; j < 4; j++) {
        float r = 1.f / (1.f + expf(-(rsv[j] + brv[j])));
        float z = 1.f / (1.f + expf(-(zsv[j] + bzv[j])));
        float ng = tanhf(ivv[j] + bnv[j] + r * (hvv[j] + bn2v[j]));
        out[j] = (1.f - z) * ng + z * hin[j];
    }
    *(float4*)&g_hf[o] = make_float4(out[0], out[1], out[2], out[3]);
    __half2 p0 = __floats2half2_rn(out[0], out[1]);
    __half2 p1 = __floats2half2_rn(out[2], out[3]);
    *(uint2*)(g_hh + o) = make_uint2(*(uint32_t*)&p0, *(uint32_t*)&p1);
}

// ---------------- pooling + classifier ----------------
__global__ void zero_feats_kernel() {
    int i = blockIdx.x * blockDim.x + threadIdx.x;
    if (i < BG * DD) g_feats[i] = 0.f;
}
__global__ void pool_kernel(const int* __restrict__ n2g) {
    int n0 = blockIdx.x * 64;
    int j  = threadIdx.x;
    if (n0 >= NN) return;
    float acc = 0.f;
    int cur = n2g[n0];
    for (int i = 0; i < 64; i++) {
        int n = n0 + i;
        if (n >= NN) break;
        int g = n2g[n];
        if (g != cur) {
            atomicAdd(&g_feats[cur * DD + j], acc);
            acc = 0.f; cur = g;
        }
        size_t o = (size_t)n * DD + j;
        acc += g_hf[o] + g_h1[o];
    }
    atomicAdd(&g_feats[cur * DD + j], acc);
}
__global__ void cls_kernel(const float* __restrict__ Wc,
                           const float* __restrict__ bc,
                           float* __restrict__ out) {
    int tid = threadIdx.x;
    if (tid >= BG * 2) return;
    int g = tid >> 1, c = tid & 1;
    float s = bc[c];
#pragma unroll 8
    for (int k = 0; k < DD; k++) s += g_feats[g * DD + k] * Wc[k * 2 + c];
    out[g * 2 + c] = s;
}

// ---------------- launch ----------------
extern "C" void kernel_launch(void* const* d_in, const int* in_sizes, int n_in,
                              void* d_out, int out_size) {
    const float* features = (const float*)d_in[0];
    const int*   src      = (const int*)  d_in[1];
    const int*   dst      = (const int*)  d_in[2];
    const int*   etype    = (const int*)  d_in[3];
    const int*   n2g      = (const int*)  d_in[4];
    const float* W_msg    = (const float*)d_in[5];
    const float* b_msg    = (const float*)d_in[6];
    const float* w_ih     = (const float*)d_in[7];
    const float* b_ih     = (const float*)d_in[8];
    const float* w_hh     = (const float*)d_in[9];
    const float* b_hh     = (const float*)d_in[10];
    const float* W_cls    = (const float*)d_in[11];
    const float* b_cls    = (const float*)d_in[12];
    float* out = (float*)d_out;

    static int inited = 0;
    if (!inited) {
        cudaFuncSetAttribute(transform_tc,
                             cudaFuncAttributeMaxDynamicSharedMemorySize, SM4);
        cudaFuncSetAttribute(gates_tc,
                             cudaFuncAttributeMaxDynamicSharedMemorySize, SM4);
        inited = 1;
    }

    // prologue — 5 launches
    fused_prep<<<(NN * DD + 255) / 256, 256>>>(features, W_msg, w_ih, w_hh);
    count_kernel<<<(EE + 255) / 256, 256>>>(dst);
    scan_a_kernel<<<NB1, 256>>>();
    scan_b_kernel<<<1, 256>>>();
    fill_kernel<<<(EE + 255) / 256, 256>>>(src, dst, etype);

    for (int s = 0; s < NSTEPS; s++) {
        transform_tc<<<dim3(TPB, TT), 256, SM4>>>(b_msg);
        gather_kernel<<<(NN + 7) / 8, 256>>>();
        gates_tc<<<dim3(RTILES, 4), 256, SM4>>>();
        gru_kernel<<<(NN * 32 + 255) / 256, 256>>>(b_ih, b_hh);
    }

    zero_feats_kernel<<<(BG * DD + 255) / 256, 256>>>();
    pool_kernel<<<(NN + 63) / 64, 128>>>(n2g);
    cls_kernel<<<1, 128>>>(W_cls, b_cls, out);
}

// round 15
// speedup vs baseline: 1.7134x; 1.0530x over previous
#include <cuda_runtime.h>
#include <cuda_fp16.h>
#include <cstdint>

#define NN 50000
#define EE 400000
#define TT 4
#define DIN 64
#define DD 128
#define BG 64
#define NSTEPS 8
#define RTILES ((NN + 127) / 128)   // 391
#define TPB 37                      // persistent transform blocks per type
#define NB1 ((NN + 255) / 256)      // 196 scan blocks

// ---------------- device scratch ----------------
__device__ float g_h1[NN * DD];                 // residual (fp32)
__device__ float g_hf[NN * DD];                 // current h (fp32 master)
__device__ __half g_t [NN * TT * DD];           // messages (fp16)
__device__ __half g_rs[NN * DD];                // gate pre-activations (fp16)
__device__ __half g_zs[NN * DD];
__device__ __half g_in[NN * DD];
__device__ __half g_hn[NN * DD];
__device__ float g_feats[BG * DD];
// single-fp16 state planes (padded one tile for OOB loads)
__device__ __half g_hh[(NN + 128) * DD];
__device__ __half g_ah[(NN + 128) * DD];
// CSR by dst
__device__ int g_cnt [NN];
__device__ int g_scan[NN];
__device__ int g_part [256];
__device__ int g_part2[256];
__device__ int g_eoff[EE];
__device__ int g_gsrc[EE];               // payload: src*512 + etype*128
// fp16 hi/lo weights, B layout [col][k]
__device__ __half g_WfH [TT * DD * DD];
__device__ __half g_WfL [TT * DD * DD];
__device__ __half g_BihH[3 * DD * DD];
__device__ __half g_BihL[3 * DD * DD];
__device__ __half g_BhhH[3 * DD * DD];
__device__ __half g_BhhL[3 * DD * DD];

// ---------------- helpers ----------------
__device__ __forceinline__ uint32_t smem_u32(const void* p) {
    return (uint32_t)__cvta_generic_to_shared(p);
}
__device__ __forceinline__ void ldsm_x4(uint32_t* r, uint32_t addr) {
    asm volatile("ldmatrix.sync.aligned.m8n8.x4.shared.b16 {%0,%1,%2,%3}, [%4];"
                 : "=r"(r[0]), "=r"(r[1]), "=r"(r[2]), "=r"(r[3]) : "r"(addr));
}
__device__ __forceinline__ void mma16816(float* d, const uint32_t* a, const uint32_t* b) {
    asm volatile(
        "mma.sync.aligned.m16n8k16.row.col.f32.f16.f16.f32 "
        "{%0,%1,%2,%3}, {%4,%5,%6,%7}, {%8,%9}, {%0,%1,%2,%3};"
        : "+f"(d[0]), "+f"(d[1]), "+f"(d[2]), "+f"(d[3])
        : "r"(a[0]), "r"(a[1]), "r"(a[2]), "r"(a[3]), "r"(b[0]), "r"(b[1]));
}
__device__ __forceinline__ void cp16(uint32_t dst, const void* src) {
    asm volatile("cp.async.cg.shared.global [%0], [%1], 16;" :: "r"(dst), "l"(src));
}
#define CP_COMMIT() asm volatile("cp.async.commit_group;" ::: "memory")
#define CP_WAIT(n)  asm volatile("cp.async.wait_group %0;" :: "n"(n) : "memory")

#define TROW 136
#define RB   (TROW * 2)            // 272B row stride
#define AT128 (128 * RB)           // 34816 per fp16 tile
#define SM4   (4 * AT128)          // 139264 (transform)
#define SM6   (6 * AT128)          // 208896 (gates)

// fp16 hi/lo split
__device__ __forceinline__ void split2(float v, __half& h, __half& l) {
    h = __float2half(v);
    l = __float2half(v - __half2float(h));
}

// async copy of one 128x128 fp16 tile, row-major source
__device__ __forceinline__ void tile_async(char* bs, const __half* __restrict__ B, int tid) {
    uint32_t ub = smem_u32(bs);
#pragma unroll
    for (int i = 0; i < 8; i++) {
        int f = tid + 256 * i;
        int r = f >> 4, c8 = (f & 15) * 8;
        cp16(ub + r * RB + c8 * 2, B + (size_t)r * DD + c8);
    }
}

// 2-term fp16 K=128 accumulate: acc += A @ (Bhi + Blo)
__device__ __forceinline__ void mma_accum_2t(float acc[2][8][4],
        uint32_t uA, uint32_t uBH, uint32_t uBL, uint32_t aoff, uint32_t boff) {
#pragma unroll
    for (int k = 0; k < 8; k++) {
        uint32_t kb = k * 32;
        uint32_t afr[2][4];
        ldsm_x4(afr[0], uA + aoff + kb);
        ldsm_x4(afr[1], uA + aoff + kb + 16 * RB);
#pragma unroll
        for (int t = 0; t < 2; t++) {
            uint32_t ub = (t == 0) ? uBH : uBL;
            uint32_t bfr[4][4];
#pragma unroll
            for (int ni = 0; ni < 4; ni++)
                ldsm_x4(bfr[ni], ub + boff + kb + ni * 16 * RB);
#pragma unroll
            for (int mi = 0; mi < 2; mi++)
#pragma unroll
                for (int ni = 0; ni < 4; ni++) {
                    mma16816(acc[mi][ni * 2 + 0], afr[mi], &bfr[ni][0]);
                    mma16816(acc[mi][ni * 2 + 1], afr[mi], &bfr[ni][2]);
                }
        }
    }
}
__device__ __forceinline__ void zero_acc(float acc[2][8][4]) {
#pragma unroll
    for (int mi = 0; mi < 2; mi++)
#pragma unroll
        for (int n8 = 0; n8 < 8; n8++)
#pragma unroll
            for (int j = 0; j < 4; j++) acc[mi][n8][j] = 0.f;
}

// ---------------- transform: persistent, grid (37, 4) -------------------
// g_t[:, tt*128:+128] = fp16( h @ Wmsg[tt]^T + bmsg[tt] ); A double-buffered
__global__ __launch_bounds__(256) void transform_tc(const float* __restrict__ bias) {
    extern __shared__ char smem[];
    char* sA0 = smem;
    char* sA1 = smem + AT128;
    char* sBH = smem + 2 * AT128;
    char* sBL = smem + 3 * AT128;
    const int tid = threadIdx.x, wid = tid >> 5, lane = tid & 31;
    const int wm = wid & 3, wn = wid >> 2;
    const int x = blockIdx.x, tt = blockIdx.y;

    tile_async(sBH, g_WfH + tt * 16384, tid);
    tile_async(sBL, g_WfL + tt * 16384, tid);
    tile_async(sA0, g_hh + (size_t)x * 128 * DD, tid);
    CP_COMMIT();

    const uint32_t aoff = (uint32_t)((wm * 32 + (lane & 15)) * RB + (lane >> 4) * 16);
    const uint32_t boff = (uint32_t)((wn * 64 + ((lane >> 4) & 1) * 8 + (lane & 7)) * RB
                                     + ((lane >> 3) & 1) * 16);
    const uint32_t uBH = smem_u32(sBH), uBL = smem_u32(sBL);
    const uint32_t uA[2] = {smem_u32(sA0), smem_u32(sA1)};
    char* pA[2] = {sA0, sA1};

    int buf = 0;
    for (int ti = x; ti < RTILES; ti += TPB) {
        int tn = ti + TPB;
        if (tn < RTILES) {
            tile_async(pA[buf ^ 1], g_hh + (size_t)tn * 128 * DD, tid);
            CP_COMMIT();
            CP_WAIT(1);
        } else {
            CP_WAIT(0);
        }
        __syncthreads();

        float acc[2][8][4];
        zero_acc(acc);
        mma_accum_2t(acc, uA[buf], uBH, uBL, aoff, boff);

        int row0 = ti * 128;
#pragma unroll
        for (int mi = 0; mi < 2; mi++) {
            int r0 = row0 + wm * 32 + mi * 16 + (lane >> 2);
#pragma unroll
            for (int n8 = 0; n8 < 8; n8++) {
                int col = wn * 64 + n8 * 8 + (lane & 3) * 2;
                float b0 = bias[tt * 128 + col], b1 = bias[tt * 128 + col + 1];
                if (r0 < NN) {
                    __half2 p = __floats2half2_rn(acc[mi][n8][0] + b0, acc[mi][n8][1] + b1);
                    *(__half2*)(g_t + (size_t)r0 * 512 + tt * 128 + col) = p;
                }
                if (r0 + 8 < NN) {
                    __half2 p = __floats2half2_rn(acc[mi][n8][2] + b0, acc[mi][n8][3] + b1);
                    *(__half2*)(g_t + (size_t)(r0 + 8) * 512 + tt * 128 + col) = p;
                }
            }
        }
        __syncthreads();
        buf ^= 1;
    }
}

// ---------------- gates: grid (391, 4), all-B-upfront, fp16 out ---------
// y=0: rs = a@ih_r + h@hh_r ; y=1: zs ; y=2: in = a@ih_n ; y=3: hn = h@hh_n
__global__ __launch_bounds__(256) void gates_tc() {
    extern __shared__ char smem[];
    char* sAa  = smem;
    char* sAh  = smem + AT128;
    char* sB1H = smem + 2 * AT128;
    char* sB1L = smem + 3 * AT128;
    char* sB2H = smem + 4 * AT128;
    char* sB2L = smem + 5 * AT128;
    const int tid = threadIdx.x, wid = tid >> 5, lane = tid & 31;
    const int wm = wid & 3, wn = wid >> 2;
    const int row0 = blockIdx.x * 128;
    const int y = blockIdx.y;
    const int ck = (y < 2) ? y : 2;

    // A tiles
    if (y != 3) tile_async(sAa, g_ah + (size_t)row0 * DD, tid);
    if (y != 2) tile_async(sAh, g_hh + (size_t)row0 * DD, tid);
    // B tiles — all upfront
    if (y == 3) {
        tile_async(sB1H, g_BhhH + 2 * 16384, tid);
        tile_async(sB1L, g_BhhL + 2 * 16384, tid);
    } else {
        tile_async(sB1H, g_BihH + ck * 16384, tid);
        tile_async(sB1L, g_BihL + ck * 16384, tid);
        if (y < 2) {
            tile_async(sB2H, g_BhhH + ck * 16384, tid);
            tile_async(sB2L, g_BhhL + ck * 16384, tid);
        }
    }
    CP_COMMIT();
    CP_WAIT(0);
    __syncthreads();

    const uint32_t aoff = (uint32_t)((wm * 32 + (lane & 15)) * RB + (lane >> 4) * 16);
    const uint32_t boff = (uint32_t)((wn * 64 + ((lane >> 4) & 1) * 8 + (lane & 7)) * RB
                                     + ((lane >> 3) & 1) * 16);
    float acc[2][8][4];
    zero_acc(acc);

    {   // pass 1: A = a (y=0,1,2) or h (y=3), B = B1
        uint32_t uA = (y == 3) ? smem_u32(sAh) : smem_u32(sAa);
        mma_accum_2t(acc, uA, smem_u32(sB1H), smem_u32(sB1L), aoff, boff);
    }
    if (y < 2) {  // pass 2: + h @ hh_ck (B2, already resident)
        mma_accum_2t(acc, smem_u32(sAh), smem_u32(sB2H), smem_u32(sB2L), aoff, boff);
    }

    __half* C = (y == 0) ? g_rs : (y == 1) ? g_zs : (y == 2) ? g_in : g_hn;
#pragma unroll
    for (int mi = 0; mi < 2; mi++) {
        int r0 = row0 + wm * 32 + mi * 16 + (lane >> 2);
#pragma unroll
        for (int n8 = 0; n8 < 8; n8++) {
            int col = wn * 64 + n8 * 8 + (lane & 3) * 2;
            if (r0 < NN) {
                __half2 p = __floats2half2_rn(acc[mi][n8][0], acc[mi][n8][1]);
                *(__half2*)(C + (size_t)r0 * DD + col) = p;
            }
            if (r0 + 8 < NN) {
                __half2 p = __floats2half2_rn(acc[mi][n8][2], acc[mi][n8][3]);
                *(__half2*)(C + (size_t)(r0 + 8) * DD + col) = p;
            }
        }
    }
}

// ---------------- fused prologue prep (launch 0) ----------------
__global__ void fused_prep(const float* __restrict__ features,
                           const float* __restrict__ Wmsg,
                           const float* __restrict__ wih,
                           const float* __restrict__ whh) {
    int idx = blockIdx.x * blockDim.x + threadIdx.x;
    if (idx < TT * DD * DD) {
        int t = idx >> 14, rem = idx & 16383, e = rem >> 7, d = rem & 127;
        __half hi, lo;
        split2(Wmsg[t * 16384 + d * 128 + e], hi, lo);
        g_WfH[idx] = hi; g_WfL[idx] = lo;
    }
    if (idx < 3 * DD * DD) {
        int c = idx >> 7, k = idx & 127;
        __half hi, lo;
        split2(wih[k * 384 + c], hi, lo);
        g_BihH[idx] = hi; g_BihL[idx] = lo;
        split2(whh[k * 384 + c], hi, lo);
        g_BhhH[idx] = hi; g_BhhL[idx] = lo;
    }
    if (idx < NN) g_cnt[idx] = 0;
    if (idx < NN * DD) {
        int n = idx >> 7, j = idx & 127;
        float v = (j < DIN) ? features[n * DIN + j] : 0.f;
        g_h1[idx] = v;
        g_hf[idx] = v;
        g_hh[idx] = __float2half(v);
    }
}

// ---------------- CSR build (by dst) ----------------
__global__ void count_kernel(const int* __restrict__ dst) {
    int e = blockIdx.x * blockDim.x + threadIdx.x;
    if (e >= EE) return;
    g_eoff[e] = atomicAdd(&g_cnt[dst[e]], 1);
}
__global__ void scan_a_kernel() {
    __shared__ int s[256];
    int b = blockIdx.x, t = threadIdx.x;
    int n = b * 256 + t;
    int v = (n < NN) ? g_cnt[n] : 0;
    s[t] = v;
    __syncthreads();
    for (int d = 1; d < 256; d <<= 1) {
        int x = (t >= d) ? s[t - d] : 0;
        __syncthreads();
        s[t] += x;
        __syncthreads();
    }
    if (n < NN) g_scan[n] = s[t] - v;
    if (t == 255) g_part[b] = s[255];
}
__global__ void scan_b_kernel() {
    __shared__ int s[256];
    int t = threadIdx.x;
    int v = (t < NB1) ? g_part[t] : 0;
    s[t] = v;
    __syncthreads();
    for (int d = 1; d < 256; d <<= 1) {
        int x = (t >= d) ? s[t - d] : 0;
        __syncthreads();
        s[t] += x;
        __syncthreads();
    }
    g_part2[t] = s[t] - v;
}
__global__ void fill_kernel(const int* __restrict__ src, const int* __restrict__ dst,
                            const int* __restrict__ et) {
    int e = blockIdx.x * blockDim.x + threadIdx.x;
    if (e >= EE) return;
    int b = dst[e];
    int pos = g_scan[b] + g_part2[b >> 8] + g_eoff[e];
    g_gsrc[pos] = src[e] * 512 + et[e] * 128;
}

// ---------------- gather: a[d] = sum fp16 msgs; writes fp16 -------------
__global__ __launch_bounds__(256) void gather_kernel() {
    int w = blockIdx.x * 8 + (threadIdx.x >> 5);
    if (w >= NN) return;
    int lane = threadIdx.x & 31;
    int lo = g_scan[w] + g_part2[w >> 8];
    int hi = (w == NN - 1) ? EE : (g_scan[w + 1] + g_part2[(w + 1) >> 8]);
    float4 a0 = make_float4(0.f, 0.f, 0.f, 0.f);
    float4 a1 = make_float4(0.f, 0.f, 0.f, 0.f);
    int i = lo;
    for (; i + 1 < hi; i += 2) {
        int s0 = g_gsrc[i], s1 = g_gsrc[i + 1];
        uint2 u0 = *(const uint2*)(g_t + s0 + lane * 4);
        uint2 u1 = *(const uint2*)(g_t + s1 + lane * 4);
        float2 p00 = __half22float2(*(__half2*)&u0.x);
        float2 p01 = __half22float2(*(__half2*)&u0.y);
        float2 p10 = __half22float2(*(__half2*)&u1.x);
        float2 p11 = __half22float2(*(__half2*)&u1.y);
        a0.x += p00.x; a0.y += p00.y; a0.z += p01.x; a0.w += p01.y;
        a1.x += p10.x; a1.y += p10.y; a1.z += p11.x; a1.w += p11.y;
    }
    if (i < hi) {
        int s0 = g_gsrc[i];
        uint2 u0 = *(const uint2*)(g_t + s0 + lane * 4);
        float2 p00 = __half22float2(*(__half2*)&u0.x);
        float2 p01 = __half22float2(*(__half2*)&u0.y);
        a0.x += p00.x; a0.y += p00.y; a0.z += p01.x; a0.w += p01.y;
    }
    a0.x += a1.x; a0.y += a1.y; a0.z += a1.z; a0.w += a1.w;

    __half2 p0 = __floats2half2_rn(a0.x, a0.y);
    __half2 p1 = __floats2half2_rn(a0.z, a0.w);
    size_t o = (size_t)w * DD + lane * 4;
    *(uint2*)(g_ah + o) = make_uint2(*(uint32_t*)&p0, *(uint32_t*)&p1);
}

// ---------------- GRU pointwise: fp16 gates in, fp32 + fp16 h out -------
__global__ void gru_kernel(const float* __restrict__ bih, const float* __restrict__ bhh) {
    int idx = blockIdx.x * blockDim.x + threadIdx.x;
    if (idx >= NN * 32) return;
    int n = idx >> 5, q = idx & 31;
    int col = q * 4;
    size_t o = (size_t)n * DD + col;
    uint2 urs = *(const uint2*)(g_rs + o);
    uint2 uzs = *(const uint2*)(g_zs + o);
    uint2 uin = *(const uint2*)(g_in + o);
    uint2 uhn = *(const uint2*)(g_hn + o);
    float2 rs0 = __half22float2(*(__half2*)&urs.x), rs1 = __half22float2(*(__half2*)&urs.y);
    float2 zs0 = __half22float2(*(__half2*)&uzs.x), zs1 = __half22float2(*(__half2*)&uzs.y);
    float2 in0 = __half22float2(*(__half2*)&uin.x), in1 = __half22float2(*(__half2*)&uin.y);
    float2 hn0 = __half22float2(*(__half2*)&uhn.x), hn1 = __half22float2(*(__half2*)&uhn.y);
    float4 h  = *(const float4*)&g_hf[o];
    float4 br  = *(const float4*)&bih[col];
    float4 br2 = *(const float4*)&bhh[col];
    float4 bz  = *(const float4*)&bih[128 + col];
    float4 bz2 = *(const float4*)&bhh[128 + col];
    float4 bn  = *(const float4*)&bih[256 + col];
    float4 bn2 = *(const float4*)&bhh[256 + col];
    float hin[4] = {h.x, h.y, h.z, h.w};
    float rsv[4] = {rs0.x, rs0.y, rs1.x, rs1.y};
    float zsv[4] = {zs0.x, zs0.y, zs1.x, zs1.y};
    float ivv[4] = {in0.x, in0.y, in1.x, in1.y};
    float hvv[4] = {hn0.x, hn0.y, hn1.x, hn1.y};
    float brv[4] = {br.x + br2.x, br.y + br2.y, br.z + br2.z, br.w + br2.w};
    float bzv[4] = {bz.x + bz2.x, bz.y + bz2.y, bz.z + bz2.z, bz.w + bz2.w};
    float bnv[4] = {bn.x, bn.y, bn.z, bn.w};
    float bn2v[4] = {bn2.x, bn2.y, bn2.z, bn2.w};
    float out[4];
#pragma unroll
    for (int j = 0; j < 4; j++) {
        float r = 1.f / (1.f + expf(-(rsv[j] + brv[j])));
        float z = 1.f / (1.f + expf(-(zsv[j] + bzv[j])));
        float ng = tanhf(ivv[j] + bnv[j] + r * (hvv[j] + bn2v[j]));
        out[j] = (1.f - z) * ng + z * hin[j];
    }
    *(float4*)&g_hf[o] = make_float4(out[0], out[1], out[2], out[3]);
    __half2 p0 = __floats2half2_rn(out[0], out[1]);
    __half2 p1 = __floats2half2_rn(out[2], out[3]);
    *(uint2*)(g_hh + o) = make_uint2(*(uint32_t*)&p0, *(uint32_t*)&p1);
}

// ---------------- pooling + classifier ----------------
__global__ void zero_feats_kernel() {
    int i = blockIdx.x * blockDim.x + threadIdx.x;
    if (i < BG * DD) g_feats[i] = 0.f;
}
__global__ void pool_kernel(const int* __restrict__ n2g) {
    int n0 = blockIdx.x * 64;
    int j  = threadIdx.x;
    if (n0 >= NN) return;
    float acc = 0.f;
    int cur = n2g[n0];
    for (int i = 0; i < 64; i++) {
        int n = n0 + i;
        if (n >= NN) break;
        int g = n2g[n];
        if (g != cur) {
            atomicAdd(&g_feats[cur * DD + j], acc);
            acc = 0.f; cur = g;
        }
        size_t o = (size_t)n * DD + j;
        acc += g_hf[o] + g_h1[o];
    }
    atomicAdd(&g_feats[cur * DD + j], acc);
}
__global__ void cls_kernel(const float* __restrict__ Wc,
                           const float* __restrict__ bc,
                           float* __restrict__ out) {
    int tid = threadIdx.x;
    if (tid >= BG * 2) return;
    int g = tid >> 1, c = tid & 1;
    float s = bc[c];
#pragma unroll 8
    for (int k = 0; k < DD; k++) s += g_feats[g * DD + k] * Wc[k * 2 + c];
    out[g * 2 + c] = s;
}

// ---------------- launch ----------------
extern "C" void kernel_launch(void* const* d_in, const int* in_sizes, int n_in,
                              void* d_out, int out_size) {
    const float* features = (const float*)d_in[0];
    const int*   src      = (const int*)  d_in[1];
    const int*   dst      = (const int*)  d_in[2];
    const int*   etype    = (const int*)  d_in[3];
    const int*   n2g      = (const int*)  d_in[4];
    const float* W_msg    = (const float*)d_in[5];
    const float* b_msg    = (const float*)d_in[6];
    const float* w_ih     = (const float*)d_in[7];
    const float* b_ih     = (const float*)d_in[8];
    const float* w_hh     = (const float*)d_in[9];
    const float* b_hh     = (const float*)d_in[10];
    const float* W_cls    = (const float*)d_in[11];
    const float* b_cls    = (const float*)d_in[12];
    float* out = (float*)d_out;

    static int inited = 0;
    if (!inited) {
        cudaFuncSetAttribute(transform_tc,
                             cudaFuncAttributeMaxDynamicSharedMemorySize, SM4);
        cudaFuncSetAttribute(gates_tc,
                             cudaFuncAttributeMaxDynamicSharedMemorySize, SM6);
        inited = 1;
    }

    // prologue — 5 launches
    fused_prep<<<(NN * DD + 255) / 256, 256>>>(features, W_msg, w_ih, w_hh);
    count_kernel<<<(EE + 255) / 256, 256>>>(dst);
    scan_a_kernel<<<NB1, 256>>>();
    scan_b_kernel<<<1, 256>>>();
    fill_kernel<<<(EE + 255) / 256, 256>>>(src, dst, etype);

    for (int s = 0; s < NSTEPS; s++) {
        transform_tc<<<dim3(TPB, TT), 256, SM4>>>(b_msg);
        gather_kernel<<<(NN + 7) / 8, 256>>>();
        gates_tc<<<dim3(RTILES, 4), 256, SM6>>>();
        gru_kernel<<<(NN * 32 + 255) / 256, 256>>>(b_ih, b_hh);
    }

    zero_feats_kernel<<<(BG * DD + 255) / 256, 256>>>();
    pool_kernel<<<(NN + 63) / 64, 128>>>(n2g);
    cls_kernel<<<1, 128>>>(W_cls, b_cls, out);
}